// round 3
// baseline (speedup 1.0000x reference)
#include <cuda_runtime.h>
#include <cuda_bf16.h>

#define N_NODES 50000
#define N_EDGES 800000
#define FD      128                   // feature dim
#define NF4     (N_NODES * (FD/4))    // float4 count of a node matrix

// ---- scratch (static __device__ arrays: allocation-free) ----
__device__ __align__(16) float g_dsum [N_NODES * FD];  // segment-sum by dst
__device__ __align__(16) float g_ssum [N_NODES * FD];  // segment-sum by src
__device__ __align__(16) float g_emean[N_NODES * FD];  // edge mean by src (layer-invariant)
__device__ __align__(16) float g_node [N_NODES * FD];  // current node embeddings
__device__ __align__(16) float g_h    [N_NODES * FD];  // EdgeSAGE hidden
__device__ __align__(16) float g_nsum [N_NODES * FD];  // neighbor scatter sum
__device__ __align__(16) float g_tmp  [N_NODES * FD];  // scaled neighbor mean
__device__ float g_degd[N_NODES];                      // in-degree (then inverse)
__device__ float g_degs[N_NODES];                      // out-degree (then inverse)
__device__ int   g_mode;                               // 0 = int32 indices, 1 = int64

// ---- detect index dtype: int64 values < 2^31 have zero high words ----
__global__ void k_detect(const int* __restrict__ idx32) {
    if (blockIdx.x == 0 && threadIdx.x == 0) {
        int nz = 0;
        #pragma unroll 8
        for (int i = 0; i < 512; i++) nz += (idx32[2 * i + 1] != 0);
        g_mode = (nz == 0) ? 1 : 0;
    }
}

__device__ __forceinline__ void load_sd(const void* __restrict__ idx, int e,
                                        int& s, int& d) {
    if (g_mode) {
        const long long* p = (const long long*)idx;
        s = (int)p[e]; d = (int)p[e + N_EDGES];
    } else {
        const int* p = (const int*)idx;
        s = p[e]; d = p[e + N_EDGES];
    }
    s = min(max(s, 0), N_NODES - 1);
    d = min(max(d, 0), N_NODES - 1);
}

// ---- zero accumulators ----
__global__ void k_zero_init() {
    int i = blockIdx.x * blockDim.x + threadIdx.x;
    if (i < NF4) {
        ((float4*)g_dsum)[i] = make_float4(0.f,0.f,0.f,0.f);
        ((float4*)g_ssum)[i] = make_float4(0.f,0.f,0.f,0.f);
    }
    if (i < N_NODES) { g_degd[i] = 0.f; g_degs[i] = 0.f; }
}

__global__ void k_zero_nsum() {
    int i = blockIdx.x * blockDim.x + threadIdx.x;
    if (i < NF4) ((float4*)g_nsum)[i] = make_float4(0.f,0.f,0.f,0.f);
}

// ---- pass 1: scatter edge_attr to both src and dst sums (one read) ----
__global__ void k_scatter_edges(const float* __restrict__ ea,
                                const void* __restrict__ idx) {
    int gid = blockIdx.x * blockDim.x + threadIdx.x;
    if (gid >= N_EDGES * 32) return;
    int e = gid >> 5, lane = gid & 31;
    int s, d; load_sd(idx, e, s, d);
    float4 v = ((const float4*)ea)[e * 32 + lane];
    float* pd = &g_dsum[(d * 32 + lane) * 4];
    float* ps = &g_ssum[(s * 32 + lane) * 4];
    atomicAdd(pd + 0, v.x); atomicAdd(pd + 1, v.y);
    atomicAdd(pd + 2, v.z); atomicAdd(pd + 3, v.w);
    atomicAdd(ps + 0, v.x); atomicAdd(ps + 1, v.y);
    atomicAdd(ps + 2, v.z); atomicAdd(ps + 3, v.w);
    if (lane == 0) {
        atomicAdd(&g_degd[d], 1.0f);
        atomicAdd(&g_degs[s], 1.0f);
    }
}

// ---- neighbor scatter: nsum[dst] += h[src] (h lives in g_h) ----
__global__ void k_scatter_neigh(const void* __restrict__ idx) {
    int gid = blockIdx.x * blockDim.x + threadIdx.x;
    if (gid >= N_EDGES * 32) return;
    int e = gid >> 5, lane = gid & 31;
    int s, d; load_sd(idx, e, s, d);
    float4 v = ((const float4*)g_h)[s * 32 + lane];
    float* p = &g_nsum[(d * 32 + lane) * 4];
    atomicAdd(p + 0, v.x); atomicAdd(p + 1, v.y);
    atomicAdd(p + 2, v.z); atomicAdd(p + 3, v.w);
}

// ---- deg -> 1/max(deg,1), in place ----
__global__ void k_inv_deg() {
    int i = blockIdx.x * blockDim.x + threadIdx.x;
    if (i < N_NODES)            g_degd[i] = 1.0f / fmaxf(g_degd[i], 1.0f);
    else if (i < 2 * N_NODES) { int j = i - N_NODES; g_degs[j] = 1.0f / fmaxf(g_degs[j], 1.0f); }
}

// ---- row-broadcast scale; sel picks (out, in, inv) triple ----
__global__ void k_scale_rows(int sel) {
    int i = blockIdx.x * blockDim.x + threadIdx.x;
    if (i >= NF4) return;
    const float4* in;
    float4* out;
    const float* inv;
    if (sel == 0)      { in = (const float4*)g_dsum; out = (float4*)g_node;  inv = g_degd; }
    else if (sel == 1) { in = (const float4*)g_ssum; out = (float4*)g_emean; inv = g_degs; }
    else               { in = (const float4*)g_nsum; out = (float4*)g_tmp;   inv = g_degd; }
    float s = inv[i >> 5];
    float4 v = in[i];
    v.x *= s; v.y *= s; v.z *= s; v.w *= s;
    out[i] = v;
}

// ---- out = relu([A|B] @ W + bias); sel picks buffers ----
// BM=64, BN=128, BK=16, 256 threads, 8x4 per thread
__global__ void __launch_bounds__(256) k_gemm_relu(
        const float* __restrict__ W, const float* __restrict__ bias, int sel) {
    const float* A;
    const float* B;
    float* out;
    if (sel == 0) { A = g_node; B = g_emean; out = g_h; }
    else          { A = g_h;    B = g_tmp;   out = g_node; }

    __shared__ float As[16][64];
    __shared__ float Bs[16][128];
    int tid = threadIdx.x;
    int m0  = blockIdx.x * 64;
    int ty = tid >> 5;        // 0..7 (row group)
    int tx = tid & 31;        // 0..31 (col group of 4)

    int arow  = tid >> 2;     // 0..63
    int acol4 = tid & 3;      // which float4 of 16-wide k chunk
    int brow  = tid >> 4;     // 0..15
    int bcol  = (tid & 15) * 8;

    float acc[8][4];
    #pragma unroll
    for (int i = 0; i < 8; i++)
        #pragma unroll
        for (int j = 0; j < 4; j++) acc[i][j] = 0.f;

    #pragma unroll 1
    for (int kt = 0; kt < 16; kt++) {
        int kbase = kt * 16;
        const float* Xsrc = (kbase < 128) ? A : B;
        int koff = kbase & 127;

        float4 av = make_float4(0.f,0.f,0.f,0.f);
        int row = m0 + arow;
        if (row < N_NODES)
            av = *(const float4*)(Xsrc + row * FD + koff + acol4 * 4);
        As[acol4*4+0][arow] = av.x;
        As[acol4*4+1][arow] = av.y;
        As[acol4*4+2][arow] = av.z;
        As[acol4*4+3][arow] = av.w;

        float4 b0 = *(const float4*)(W + (kbase + brow) * FD + bcol);
        float4 b1 = *(const float4*)(W + (kbase + brow) * FD + bcol + 4);
        *(float4*)&Bs[brow][bcol]     = b0;
        *(float4*)&Bs[brow][bcol + 4] = b1;

        __syncthreads();

        #pragma unroll
        for (int kk = 0; kk < 16; kk++) {
            float a[8], b[4];
            *(float4*)&a[0] = *(const float4*)&As[kk][ty*8];
            *(float4*)&a[4] = *(const float4*)&As[kk][ty*8 + 4];
            *(float4*)&b[0] = *(const float4*)&Bs[kk][tx*4];
            #pragma unroll
            for (int i = 0; i < 8; i++)
                #pragma unroll
                for (int j = 0; j < 4; j++)
                    acc[i][j] = fmaf(a[i], b[j], acc[i][j]);
        }
        __syncthreads();
    }

    float4 bia = *(const float4*)(bias + tx * 4);
    #pragma unroll
    for (int i = 0; i < 8; i++) {
        int row = m0 + ty * 8 + i;
        if (row < N_NODES) {
            float4 o;
            o.x = fmaxf(acc[i][0] + bia.x, 0.f);
            o.y = fmaxf(acc[i][1] + bia.y, 0.f);
            o.z = fmaxf(acc[i][2] + bia.z, 0.f);
            o.w = fmaxf(acc[i][3] + bia.w, 0.f);
            *(float4*)(out + row * FD + tx * 4) = o;
        }
    }
}

// ---- final: edge embeddings + logits (warp per edge); node emb from g_node ----
__global__ void k_edge_out(const void* __restrict__ idx,
                           const float* __restrict__ Wf,
                           const float* __restrict__ bf,
                           float* __restrict__ logits,
                           float* __restrict__ emb) {
    int gid = blockIdx.x * blockDim.x + threadIdx.x;
    if (gid >= N_EDGES * 32) return;
    int e = gid >> 5, lane = gid & 31;
    int s, d; load_sd(idx, e, s, d);
    float4 sv = ((const float4*)g_node)[s * 32 + lane];
    float4 dv = ((const float4*)g_node)[d * 32 + lane];
    ((float4*)emb)[e * 64 + lane]      = sv;
    ((float4*)emb)[e * 64 + 32 + lane] = dv;
    const float4* wf4 = (const float4*)Wf;
    float4 w0 = __ldg(wf4 + lane);
    float4 w1 = __ldg(wf4 + 32 + lane);
    float p = sv.x*w0.x + sv.y*w0.y + sv.z*w0.z + sv.w*w0.w
            + dv.x*w1.x + dv.y*w1.y + dv.z*w1.z + dv.w*w1.w;
    #pragma unroll
    for (int o = 16; o > 0; o >>= 1) p += __shfl_down_sync(0xffffffffu, p, o);
    if (lane == 0) logits[e] = p + bf[0];
}

// ---- copy node embeddings (g_node) into output ----
__global__ void k_copy_node(float* __restrict__ dst) {
    int i = blockIdx.x * blockDim.x + threadIdx.x;
    if (i < NF4) ((float4*)dst)[i] = ((const float4*)g_node)[i];
}

extern "C" void kernel_launch(void* const* d_in, const int* in_sizes, int n_in,
                              void* d_out, int out_size) {
    const float* edge_attr = (const float*)d_in[0];
    const void*  eidx      = d_in[1];                 // int32 or int64, detected on device
    const float* W0e = (const float*)d_in[2];
    const float* b0e = (const float*)d_in[3];
    const float* W0n = (const float*)d_in[4];
    const float* b0n = (const float*)d_in[5];
    const float* W1e = (const float*)d_in[6];
    const float* b1e = (const float*)d_in[7];
    const float* W1n = (const float*)d_in[8];
    const float* b1n = (const float*)d_in[9];
    const float* Wf  = (const float*)d_in[10];
    const float* bf  = (const float*)d_in[11];

    float* out_logits = (float*)d_out;
    float* out_emb    = out_logits + N_EDGES;
    float* out_node   = out_emb + (size_t)N_EDGES * 2 * FD;

    const int TB = 256;
    int gz   = (NF4 + TB - 1) / TB;               // zero / scale grids
    int gsc  = (N_EDGES * 32 + TB - 1) / TB;      // scatter grids
    int gin  = (2 * N_NODES + TB - 1) / TB;
    int ggm  = (N_NODES + 63) / 64;               // 782 gemm blocks

    // dtype detection + init segment sums + degrees
    k_detect<<<1, 32>>>((const int*)eidx);
    k_zero_init<<<gz, TB>>>();
    k_scatter_edges<<<gsc, TB>>>(edge_attr, eidx);
    k_inv_deg<<<gin, TB>>>();
    k_scale_rows<<<gz, TB>>>(0);   // node_attr = mean of edge_attr by dst
    k_scale_rows<<<gz, TB>>>(1);   // emean = mean of edge_attr by src (both layers)

    // layer 0
    k_gemm_relu<<<ggm, TB>>>(W0e, b0e, 0);
    k_zero_nsum<<<gz, TB>>>();
    k_scatter_neigh<<<gsc, TB>>>(eidx);
    k_scale_rows<<<gz, TB>>>(2);
    k_gemm_relu<<<ggm, TB>>>(W0n, b0n, 1);

    // layer 1
    k_gemm_relu<<<ggm, TB>>>(W1e, b1e, 0);
    k_zero_nsum<<<gz, TB>>>();
    k_scatter_neigh<<<gsc, TB>>>(eidx);
    k_scale_rows<<<gz, TB>>>(2);
    k_gemm_relu<<<ggm, TB>>>(W1n, b1n, 1);

    // outputs
    k_edge_out<<<gsc, TB>>>(eidx, Wf, bf, out_logits, out_emb);
    k_copy_node<<<gz, TB>>>(out_node);
}

// round 5
// speedup vs baseline: 2.8973x; 2.8973x over previous
#include <cuda_runtime.h>
#include <cuda_bf16.h>

#define N_NODES 50000
#define N_EDGES 800000
#define FD      128                   // feature dim
#define NF4     (N_NODES * (FD/4))    // float4 count of a node matrix

// ---- scratch (static __device__ arrays: allocation-free) ----
__device__ __align__(16) float g_node [N_NODES * FD];  // current node embeddings
__device__ __align__(16) float g_emean[N_NODES * FD];  // edge mean by src (layer-invariant)
__device__ __align__(16) float g_h    [N_NODES * FD];  // EdgeSAGE hidden
__device__ __align__(16) float g_tmp  [N_NODES * FD];  // neighbor mean
__device__ int g_cnt_d[N_NODES];                       // in-degree counts
__device__ int g_cnt_s[N_NODES];                       // out-degree counts
__device__ int g_off_d[N_NODES];                       // dst CSR range begin (unordered alloc)
__device__ int g_off_s[N_NODES];                       // src CSR range begin
__device__ int g_cur_d[N_NODES];                       // fill cursors
__device__ int g_cur_s[N_NODES];
__device__ int g_lst_d[N_EDGES];                       // edge ids grouped by dst
__device__ int g_src_d[N_EDGES];                       // src node of those edges
__device__ int g_lst_s[N_EDGES];                       // edge ids grouped by src
__device__ int g_tot_d;                                // range allocator totals
__device__ int g_tot_s;
__device__ int g_mode;                                 // 0 = int32 indices, 1 = int64

// ---- detect index dtype: int64 values < 2^31 have zero high words ----
__global__ void k_detect(const int* __restrict__ idx32) {
    if (blockIdx.x == 0 && threadIdx.x == 0) {
        int nz = 0;
        for (int i = 0; i < 512; i++) nz += (idx32[2 * i + 1] != 0);
        g_mode = (nz == 0) ? 1 : 0;
    }
}

__device__ __forceinline__ void load_sd(const void* __restrict__ idx, int e,
                                        int& s, int& d) {
    if (g_mode) {
        const long long* p = (const long long*)idx;
        s = (int)p[e]; d = (int)p[e + N_EDGES];
    } else {
        const int* p = (const int*)idx;
        s = p[e]; d = p[e + N_EDGES];
    }
    s = min(max(s, 0), N_NODES - 1);
    d = min(max(d, 0), N_NODES - 1);
}

// ---- CSR build: zero counts + totals ----
__global__ void k_zero_cnt() {
    int i = blockIdx.x * blockDim.x + threadIdx.x;
    if (i < N_NODES) { g_cnt_d[i] = 0; g_cnt_s[i] = 0; }
    if (i == 0) { g_tot_d = 0; g_tot_s = 0; }
}

// ---- CSR build: histogram ----
__global__ void k_hist(const void* __restrict__ idx) {
    int e = blockIdx.x * blockDim.x + threadIdx.x;
    if (e >= N_EDGES) return;
    int s, d; load_sd(idx, e, s, d);
    atomicAdd(&g_cnt_d[d], 1);
    atomicAdd(&g_cnt_s[s], 1);
}

// ---- CSR build: allocate a private range per node (order irrelevant) ----
__global__ void k_alloc() {
    int i = blockIdx.x * blockDim.x + threadIdx.x;
    if (i >= N_NODES) return;
    int cd = g_cnt_d[i];
    int od = atomicAdd(&g_tot_d, cd);
    g_off_d[i] = od;
    g_cur_d[i] = od;
    int cs = g_cnt_s[i];
    int os = atomicAdd(&g_tot_s, cs);
    g_off_s[i] = os;
    g_cur_s[i] = os;
}

// ---- CSR build: fill lists ----
__global__ void k_fill(const void* __restrict__ idx) {
    int e = blockIdx.x * blockDim.x + threadIdx.x;
    if (e >= N_EDGES) return;
    int s, d; load_sd(idx, e, s, d);
    int pd = atomicAdd(&g_cur_d[d], 1);
    pd = min(max(pd, 0), N_EDGES - 1);
    g_lst_d[pd] = e;
    g_src_d[pd] = s;
    int ps = atomicAdd(&g_cur_s[s], 1);
    ps = min(max(ps, 0), N_EDGES - 1);
    g_lst_s[ps] = e;
}

// ---- pass 1: both segment means via gather (warp per node) ----
__global__ void k_gather_means(const float* __restrict__ ea) {
    int gid = blockIdx.x * blockDim.x + threadIdx.x;
    int w = gid >> 5, lane = gid & 31;
    if (w >= N_NODES) return;
    const float4* ea4 = (const float4*)ea;

    // mean of edge_attr over incoming edges (by dst) -> g_node
    {
        int b = g_off_d[w];
        int n = g_cnt_d[w];
        int e = min(b + n, N_EDGES);
        float4 acc = make_float4(0.f, 0.f, 0.f, 0.f);
        for (int i = b; i < e; i++) {
            int eid = min(max(g_lst_d[i], 0), N_EDGES - 1);
            float4 v = ea4[(size_t)eid * 32 + lane];
            acc.x += v.x; acc.y += v.y; acc.z += v.z; acc.w += v.w;
        }
        float inv = 1.0f / fmaxf((float)n, 1.0f);
        acc.x *= inv; acc.y *= inv; acc.z *= inv; acc.w *= inv;
        ((float4*)g_node)[w * 32 + lane] = acc;
    }
    // mean of edge_attr over outgoing edges (by src) -> g_emean
    {
        int b = g_off_s[w];
        int n = g_cnt_s[w];
        int e = min(b + n, N_EDGES);
        float4 acc = make_float4(0.f, 0.f, 0.f, 0.f);
        for (int i = b; i < e; i++) {
            int eid = min(max(g_lst_s[i], 0), N_EDGES - 1);
            float4 v = ea4[(size_t)eid * 32 + lane];
            acc.x += v.x; acc.y += v.y; acc.z += v.z; acc.w += v.w;
        }
        float inv = 1.0f / fmaxf((float)n, 1.0f);
        acc.x *= inv; acc.y *= inv; acc.z *= inv; acc.w *= inv;
        ((float4*)g_emean)[w * 32 + lane] = acc;
    }
}

// ---- neighbor mean: tmp[n] = mean over in-edges of h[src(e)] ----
__global__ void k_gather_neigh() {
    int gid = blockIdx.x * blockDim.x + threadIdx.x;
    int w = gid >> 5, lane = gid & 31;
    if (w >= N_NODES) return;
    const float4* h4 = (const float4*)g_h;
    int b = g_off_d[w];
    int n = g_cnt_d[w];
    int e = min(b + n, N_EDGES);
    float4 acc = make_float4(0.f, 0.f, 0.f, 0.f);
    for (int i = b; i < e; i++) {
        int s = min(max(g_src_d[i], 0), N_NODES - 1);
        float4 v = h4[(size_t)s * 32 + lane];
        acc.x += v.x; acc.y += v.y; acc.z += v.z; acc.w += v.w;
    }
    float inv = 1.0f / fmaxf((float)n, 1.0f);
    acc.x *= inv; acc.y *= inv; acc.z *= inv; acc.w *= inv;
    ((float4*)g_tmp)[w * 32 + lane] = acc;
}

// ---- out = relu([A|B] @ W + bias); sel picks buffers ----
// sel 0: A=g_node, B=g_emean, out=g_h
// sel 1: A=g_h,    B=g_tmp,   out=g_node
// BM=64, BN=128, BK=16, 256 threads, 8x4 per thread
__global__ void __launch_bounds__(256) k_gemm_relu(
        const float* __restrict__ W, const float* __restrict__ bias, int sel) {
    const float* A;
    const float* B;
    float* out;
    if (sel == 0) { A = g_node; B = g_emean; out = g_h; }
    else          { A = g_h;    B = g_tmp;   out = g_node; }

    __shared__ float As[16][64];
    __shared__ float Bs[16][128];
    int tid = threadIdx.x;
    int m0  = blockIdx.x * 64;
    int ty = tid >> 5;        // 0..7 (row group)
    int tx = tid & 31;        // 0..31 (col group of 4)

    int arow  = tid >> 2;     // 0..63
    int acol4 = tid & 3;      // which float4 of 16-wide k chunk
    int brow  = tid >> 4;     // 0..15
    int bcol  = (tid & 15) * 8;

    float acc[8][4];
    #pragma unroll
    for (int i = 0; i < 8; i++)
        #pragma unroll
        for (int j = 0; j < 4; j++) acc[i][j] = 0.f;

    #pragma unroll 1
    for (int kt = 0; kt < 16; kt++) {
        int kbase = kt * 16;
        const float* Xsrc = (kbase < 128) ? A : B;
        int koff = kbase & 127;

        float4 av = make_float4(0.f,0.f,0.f,0.f);
        int row = m0 + arow;
        if (row < N_NODES)
            av = *(const float4*)(Xsrc + row * FD + koff + acol4 * 4);
        As[acol4*4+0][arow] = av.x;
        As[acol4*4+1][arow] = av.y;
        As[acol4*4+2][arow] = av.z;
        As[acol4*4+3][arow] = av.w;

        float4 b0 = *(const float4*)(W + (kbase + brow) * FD + bcol);
        float4 b1 = *(const float4*)(W + (kbase + brow) * FD + bcol + 4);
        *(float4*)&Bs[brow][bcol]     = b0;
        *(float4*)&Bs[brow][bcol + 4] = b1;

        __syncthreads();

        #pragma unroll
        for (int kk = 0; kk < 16; kk++) {
            float a[8], b[4];
            *(float4*)&a[0] = *(const float4*)&As[kk][ty*8];
            *(float4*)&a[4] = *(const float4*)&As[kk][ty*8 + 4];
            *(float4*)&b[0] = *(const float4*)&Bs[kk][tx*4];
            #pragma unroll
            for (int i = 0; i < 8; i++)
                #pragma unroll
                for (int j = 0; j < 4; j++)
                    acc[i][j] = fmaf(a[i], b[j], acc[i][j]);
        }
        __syncthreads();
    }

    float4 bia = *(const float4*)(bias + tx * 4);
    #pragma unroll
    for (int i = 0; i < 8; i++) {
        int row = m0 + ty * 8 + i;
        if (row < N_NODES) {
            float4 o;
            o.x = fmaxf(acc[i][0] + bia.x, 0.f);
            o.y = fmaxf(acc[i][1] + bia.y, 0.f);
            o.z = fmaxf(acc[i][2] + bia.z, 0.f);
            o.w = fmaxf(acc[i][3] + bia.w, 0.f);
            *(float4*)(out + row * FD + tx * 4) = o;
        }
    }
}

// ---- final: edge embeddings + logits (warp per edge); node emb from g_node ----
__global__ void k_edge_out(const void* __restrict__ idx,
                           const float* __restrict__ Wf,
                           const float* __restrict__ bf,
                           float* __restrict__ logits,
                           float* __restrict__ emb) {
    int gid = blockIdx.x * blockDim.x + threadIdx.x;
    if (gid >= N_EDGES * 32) return;
    int e = gid >> 5, lane = gid & 31;
    int s, d; load_sd(idx, e, s, d);
    float4 sv = ((const float4*)g_node)[(size_t)s * 32 + lane];
    float4 dv = ((const float4*)g_node)[(size_t)d * 32 + lane];
    ((float4*)emb)[(size_t)e * 64 + lane]      = sv;
    ((float4*)emb)[(size_t)e * 64 + 32 + lane] = dv;
    const float4* wf4 = (const float4*)Wf;
    float4 w0 = __ldg(wf4 + lane);
    float4 w1 = __ldg(wf4 + 32 + lane);
    float p = sv.x*w0.x + sv.y*w0.y + sv.z*w0.z + sv.w*w0.w
            + dv.x*w1.x + dv.y*w1.y + dv.z*w1.z + dv.w*w1.w;
    #pragma unroll
    for (int o = 16; o > 0; o >>= 1) p += __shfl_down_sync(0xffffffffu, p, o);
    if (lane == 0) logits[e] = p + bf[0];
}

// ---- copy node embeddings (g_node) into output ----
__global__ void k_copy_node(float* __restrict__ dst) {
    int i = blockIdx.x * blockDim.x + threadIdx.x;
    if (i < NF4) ((float4*)dst)[i] = ((const float4*)g_node)[i];
}

extern "C" void kernel_launch(void* const* d_in, const int* in_sizes, int n_in,
                              void* d_out, int out_size) {
    const float* edge_attr = (const float*)d_in[0];
    const void*  eidx      = d_in[1];                 // int32 or int64, detected on device
    const float* W0e = (const float*)d_in[2];
    const float* b0e = (const float*)d_in[3];
    const float* W0n = (const float*)d_in[4];
    const float* b0n = (const float*)d_in[5];
    const float* W1e = (const float*)d_in[6];
    const float* b1e = (const float*)d_in[7];
    const float* W1n = (const float*)d_in[8];
    const float* b1n = (const float*)d_in[9];
    const float* Wf  = (const float*)d_in[10];
    const float* bf  = (const float*)d_in[11];

    float* out_logits = (float*)d_out;
    float* out_emb    = out_logits + N_EDGES;
    float* out_node   = out_emb + (size_t)N_EDGES * 2 * FD;

    const int TB = 256;
    int gn   = (N_NODES + TB - 1) / TB;             // per-node grids
    int ge   = (N_EDGES + TB - 1) / TB;             // per-edge grids
    int gw   = (N_NODES * 32 + TB - 1) / TB;        // warp-per-node grids
    int gsc  = (N_EDGES * 32 + TB - 1) / TB;        // warp-per-edge grids
    int gz   = (NF4 + TB - 1) / TB;
    int ggm  = (N_NODES + 63) / 64;                 // 782 gemm blocks

    // CSR build (scan-free: atomic range allocation)
    k_detect<<<1, 32>>>((const int*)eidx);
    k_zero_cnt<<<gn, TB>>>();
    k_hist<<<ge, TB>>>(eidx);
    k_alloc<<<gn, TB>>>();
    k_fill<<<ge, TB>>>(eidx);

    // initial means (node_attr by dst, emean by src)
    k_gather_means<<<gw, TB>>>(edge_attr);

    // layer 0
    k_gemm_relu<<<ggm, TB>>>(W0e, b0e, 0);
    k_gather_neigh<<<gw, TB>>>();
    k_gemm_relu<<<ggm, TB>>>(W0n, b0n, 1);

    // layer 1
    k_gemm_relu<<<ggm, TB>>>(W1e, b1e, 0);
    k_gather_neigh<<<gw, TB>>>();
    k_gemm_relu<<<ggm, TB>>>(W1n, b1n, 1);

    // outputs
    k_edge_out<<<gsc, TB>>>(eidx, Wf, bf, out_logits, out_emb);
    k_copy_node<<<gz, TB>>>(out_node);
}